// round 7
// baseline (speedup 1.0000x reference)
#include <cuda_runtime.h>
#include <stdint.h>

#define D_IN   256
#define D_HID  64
#define D_EMB  32
#define MAX_NODES 100000

// Scratch (static __device__ — no allocation allowed)
__device__ float g_H [MAX_NODES * D_HID];   // x @ W1
__device__ float g_S1[MAX_NODES * D_HID];   // A @ H
__device__ float g_Z1[MAX_NODES * D_EMB];   // relu(S1+b1) @ W2
__device__ float g_S2[MAX_NODES * D_EMB];   // A @ Z1

// ---------------------------------------------------------------------------
// TF32 helpers
// ---------------------------------------------------------------------------
__device__ __forceinline__ unsigned f2tf32(float f) {
    unsigned r;
    asm("cvt.rna.tf32.f32 %0, %1;" : "=r"(r) : "f"(f));
    return r;
}
__device__ __forceinline__ unsigned bits2tf32(unsigned b) {
    unsigned r;
    asm("cvt.rna.tf32.f32 %0, %1;" : "=r"(r) : "r"(b));
    return r;
}

__device__ __forceinline__ void mma_tf32(
    float& d0, float& d1, float& d2, float& d3,
    unsigned a0, unsigned a1, unsigned a2, unsigned a3,
    unsigned b0, unsigned b1)
{
    asm volatile(
        "mma.sync.aligned.m16n8k8.row.col.f32.tf32.tf32.f32 "
        "{%0,%1,%2,%3}, {%4,%5,%6,%7}, {%8,%9}, {%0,%1,%2,%3};"
        : "+f"(d0), "+f"(d1), "+f"(d2), "+f"(d3)
        : "r"(a0), "r"(a1), "r"(a2), "r"(a3), "r"(b0), "r"(b1));
}

__device__ __forceinline__ void cp_async16(unsigned smem_addr, const void* gptr) {
    asm volatile("cp.async.cg.shared.global [%0], [%1], 16;"
                 :: "r"(smem_addr), "l"(gptr));
}

// ---------------------------------------------------------------------------
// GEMM1 (TF32 + cp.async double buffer + fused zeroing + rna-cvt on A frags)
//   H = x @ W1   [n,256] @ [256,64]
// ---------------------------------------------------------------------------
#define W_STRIDE 72
#define X_STRIDE 36
#define W_WORDS  (256 * W_STRIDE)
#define X_WORDS  (128 * X_STRIDE)
#define GEMM1_SMEM ((W_WORDS + 2 * X_WORDS) * 4)

__global__ __launch_bounds__(256) void gemm1_tf32_v3(
    const float* __restrict__ x, const float* __restrict__ W1, int n)
{
    extern __shared__ unsigned smem[];
    unsigned* Wsh = smem;                       // [256][72]
    float*    xsf = (float*)(smem + W_WORDS);   // [2][128][36]

    int tid  = threadIdx.x;
    int warp = tid >> 5;
    int lane = tid & 31;
    int row_base = blockIdx.x * 128;
    int wm   = warp * 16;
    int qrow = lane >> 2;
    int qcol = lane & 3;

    unsigned xs_base;
    asm("{ .reg .u64 t; cvta.to.shared.u64 t, %1; cvt.u32.u64 %0, t; }"
        : "=r"(xs_base) : "l"(xsf));

    // prefetch x chunk 0 into buffer 0
    #pragma unroll
    for (int l = 0; l < 4; l++) {
        int flat = tid + l * 256;
        int r    = flat >> 3;
        int c4   = flat & 7;
        int grow = row_base + r; if (grow >= n) grow = n - 1;
        cp_async16(xs_base + (unsigned)(r * X_STRIDE + c4 * 4) * 4,
                   x + (size_t)grow * D_IN + c4 * 4);
    }
    asm volatile("cp.async.commit_group;");

    // stage whole W1 (tf32, rna)
    #pragma unroll
    for (int l = 0; l < 16; l++) {
        int flat = tid + l * 256;
        int k  = flat >> 4;
        int cc = (flat & 15) * 4;
        float4 w = __ldg((const float4*)(W1 + (size_t)k * 64 + cc));
        Wsh[k * W_STRIDE + cc + 0] = f2tf32(w.x);
        Wsh[k * W_STRIDE + cc + 1] = f2tf32(w.y);
        Wsh[k * W_STRIDE + cc + 2] = f2tf32(w.z);
        Wsh[k * W_STRIDE + cc + 3] = f2tf32(w.w);
    }

    // fused zeroing of S1 / S2
    {
        int gtid = blockIdx.x * 256 + tid;
        int nthr = gridDim.x * 256;
        float4 z = make_float4(0.f, 0.f, 0.f, 0.f);
        for (int i = gtid; i < n * 16; i += nthr) ((float4*)g_S1)[i] = z;
        for (int i = gtid; i < n * 8;  i += nthr) ((float4*)g_S2)[i] = z;
    }

    float c[8][4];
    #pragma unroll
    for (int nt = 0; nt < 8; nt++)
        #pragma unroll
        for (int i = 0; i < 4; i++) c[nt][i] = 0.f;

    #pragma unroll
    for (int kc = 0; kc < 8; kc++) {
        if (kc + 1 < 8) {
            int buf = (kc + 1) & 1;
            #pragma unroll
            for (int l = 0; l < 4; l++) {
                int flat = tid + l * 256;
                int r    = flat >> 3;
                int c4   = flat & 7;
                int grow = row_base + r; if (grow >= n) grow = n - 1;
                cp_async16(xs_base + (unsigned)(buf * X_WORDS + r * X_STRIDE + c4 * 4) * 4,
                           x + (size_t)grow * D_IN + (kc + 1) * 32 + c4 * 4);
            }
            asm volatile("cp.async.commit_group;");
            asm volatile("cp.async.wait_group 1;");
        } else {
            asm volatile("cp.async.wait_group 0;");
        }
        __syncthreads();

        const unsigned* xb = (const unsigned*)(xsf + (kc & 1) * X_WORDS);
        #pragma unroll
        for (int k8 = 0; k8 < 4; k8++) {
            int ar = wm + qrow;
            int ac = k8 * 8 + qcol;
            unsigned a0 = bits2tf32(xb[(ar    ) * X_STRIDE + ac    ]);
            unsigned a1 = bits2tf32(xb[(ar + 8) * X_STRIDE + ac    ]);
            unsigned a2 = bits2tf32(xb[(ar    ) * X_STRIDE + ac + 4]);
            unsigned a3 = bits2tf32(xb[(ar + 8) * X_STRIDE + ac + 4]);
            int kg = kc * 32 + k8 * 8 + qcol;
            #pragma unroll
            for (int nt = 0; nt < 8; nt++) {
                unsigned b0 = Wsh[(kg    ) * W_STRIDE + nt * 8 + qrow];
                unsigned b1 = Wsh[(kg + 4) * W_STRIDE + nt * 8 + qrow];
                mma_tf32(c[nt][0], c[nt][1], c[nt][2], c[nt][3],
                         a0, a1, a2, a3, b0, b1);
            }
        }
        __syncthreads();
    }

    int r0 = row_base + wm + qrow;
    int cb = qcol * 2;
    #pragma unroll
    for (int nt = 0; nt < 8; nt++) {
        if (r0 < n)
            *(float2*)(g_H + (size_t)r0 * D_HID + nt*8 + cb) =
                make_float2(c[nt][0], c[nt][1]);
        if (r0 + 8 < n)
            *(float2*)(g_H + (size_t)(r0 + 8) * D_HID + nt*8 + cb) =
                make_float2(c[nt][2], c[nt][3]);
    }
}

// ---------------------------------------------------------------------------
// red.v4 helper
// ---------------------------------------------------------------------------
__device__ __forceinline__ void red_add_v4(float* p, float4 v) {
    asm volatile("red.global.add.v4.f32 [%0], {%1,%2,%3,%4};"
                 :: "l"(p), "f"(v.x), "f"(v.y), "f"(v.z), "f"(v.w)
                 : "memory");
}

// ---------------------------------------------------------------------------
// SpMM d=64: 16 lanes per edge-group, 4 edges per thread, vector index loads.
// ---------------------------------------------------------------------------
__global__ __launch_bounds__(256) void spmm64_kernel(
    const int* __restrict__ src, const int* __restrict__ dst,
    const float* __restrict__ val, int nnz)
{
    int t = blockIdx.x * blockDim.x + threadIdx.x;
    int c = t & 15;
    int g = t >> 4;
    int base = g * 4;
    if (base >= nnz) return;

    int4 s4, d4; float4 v4;
    if (base + 3 < nnz) {
        s4 = __ldg((const int4*)src + g);
        d4 = __ldg((const int4*)dst + g);
        v4 = __ldg((const float4*)val + g);
    } else {
        int e1 = (base+1 < nnz) ? base+1 : base;
        int e2 = (base+2 < nnz) ? base+2 : base;
        int e3 = (base+3 < nnz) ? base+3 : base;
        s4 = make_int4(__ldg(src+base), __ldg(src+e1), __ldg(src+e2), __ldg(src+e3));
        d4 = make_int4(__ldg(dst+base), __ldg(dst+e1), __ldg(dst+e2), __ldg(dst+e3));
        v4 = make_float4(__ldg(val+base),
                         (base+1 < nnz) ? __ldg(val+e1) : 0.f,
                         (base+2 < nnz) ? __ldg(val+e2) : 0.f,
                         (base+3 < nnz) ? __ldg(val+e3) : 0.f);
    }

    float4 h0 = __ldg((const float4*)(g_H + (size_t)s4.x * D_HID) + c);
    float4 h1 = __ldg((const float4*)(g_H + (size_t)s4.y * D_HID) + c);
    float4 h2 = __ldg((const float4*)(g_H + (size_t)s4.z * D_HID) + c);
    float4 h3 = __ldg((const float4*)(g_H + (size_t)s4.w * D_HID) + c);

    red_add_v4(g_S1 + (size_t)d4.x * D_HID + c*4, make_float4(v4.x*h0.x, v4.x*h0.y, v4.x*h0.z, v4.x*h0.w));
    red_add_v4(g_S1 + (size_t)d4.y * D_HID + c*4, make_float4(v4.y*h1.x, v4.y*h1.y, v4.y*h1.z, v4.y*h1.w));
    red_add_v4(g_S1 + (size_t)d4.z * D_HID + c*4, make_float4(v4.z*h2.x, v4.z*h2.y, v4.z*h2.z, v4.z*h2.w));
    red_add_v4(g_S1 + (size_t)d4.w * D_HID + c*4, make_float4(v4.w*h3.x, v4.w*h3.y, v4.w*h3.z, v4.w*h3.w));
}

// ---------------------------------------------------------------------------
// GEMM2: Z1 = relu(S1 + b1) @ W2   [n,64] @ [64,32]
// ---------------------------------------------------------------------------
__global__ __launch_bounds__(256) void gemm2_kernel(
    const float* __restrict__ b1, const float* __restrict__ W2, int n)
{
    __shared__ float zs[64][65];
    __shared__ float ws[64][32];

    int tid = threadIdx.x;
    int row_base = blockIdx.x * 64;

    #pragma unroll
    for (int l = 0; l < 4; l++) {
        int flat = tid + l * 256;
        int r  = flat >> 4;
        int c4 = flat & 15;
        float4 v = make_float4(0.f,0.f,0.f,0.f);
        if (row_base + r < n)
            v = *(const float4*)(g_S1 + (size_t)row_base * D_HID + (size_t)flat * 4);
        float4 bb = __ldg((const float4*)b1 + c4);
        v.x = fmaxf(v.x + bb.x, 0.f);
        v.y = fmaxf(v.y + bb.y, 0.f);
        v.z = fmaxf(v.z + bb.z, 0.f);
        v.w = fmaxf(v.w + bb.w, 0.f);
        zs[r][c4*4+0] = v.x; zs[r][c4*4+1] = v.y;
        zs[r][c4*4+2] = v.z; zs[r][c4*4+3] = v.w;
    }
    #pragma unroll
    for (int l = 0; l < 2; l++) {
        int flat = tid + l * 256;
        ((float4*)&ws[0][0])[flat] = __ldg((const float4*)W2 + flat);
    }
    __syncthreads();

    int ty = tid >> 3;
    int tx = tid & 7;
    int col = tx * 4;

    float a00=0,a01=0,a02=0,a03=0;
    float a10=0,a11=0,a12=0,a13=0;

    #pragma unroll 16
    for (int kk = 0; kk < 64; kk++) {
        float z0 = zs[ty*2+0][kk];
        float z1 = zs[ty*2+1][kk];
        float4 b = *(float4*)&ws[kk][col];
        a00 += z0*b.x; a01 += z0*b.y; a02 += z0*b.z; a03 += z0*b.w;
        a10 += z1*b.x; a11 += z1*b.y; a12 += z1*b.z; a13 += z1*b.w;
    }

    int r0 = row_base + ty*2;
    if (r0 + 0 < n) *(float4*)(g_Z1 + (size_t)(r0+0)*D_EMB + col) = make_float4(a00,a01,a02,a03);
    if (r0 + 1 < n) *(float4*)(g_Z1 + (size_t)(r0+1)*D_EMB + col) = make_float4(a10,a11,a12,a13);
}

// ---------------------------------------------------------------------------
// SpMM d=32: 8 lanes per edge-group, 4 edges per thread, vector index loads.
// ---------------------------------------------------------------------------
__global__ __launch_bounds__(256) void spmm32_kernel(
    const int* __restrict__ src, const int* __restrict__ dst,
    const float* __restrict__ val, int nnz)
{
    int t = blockIdx.x * blockDim.x + threadIdx.x;
    int c = t & 7;
    int g = t >> 3;
    int base = g * 4;
    if (base >= nnz) return;

    int4 s4, d4; float4 v4;
    if (base + 3 < nnz) {
        s4 = __ldg((const int4*)src + g);
        d4 = __ldg((const int4*)dst + g);
        v4 = __ldg((const float4*)val + g);
    } else {
        int e1 = (base+1 < nnz) ? base+1 : base;
        int e2 = (base+2 < nnz) ? base+2 : base;
        int e3 = (base+3 < nnz) ? base+3 : base;
        s4 = make_int4(__ldg(src+base), __ldg(src+e1), __ldg(src+e2), __ldg(src+e3));
        d4 = make_int4(__ldg(dst+base), __ldg(dst+e1), __ldg(dst+e2), __ldg(dst+e3));
        v4 = make_float4(__ldg(val+base),
                         (base+1 < nnz) ? __ldg(val+e1) : 0.f,
                         (base+2 < nnz) ? __ldg(val+e2) : 0.f,
                         (base+3 < nnz) ? __ldg(val+e3) : 0.f);
    }

    float4 h0 = __ldg((const float4*)(g_Z1 + (size_t)s4.x * D_EMB) + c);
    float4 h1 = __ldg((const float4*)(g_Z1 + (size_t)s4.y * D_EMB) + c);
    float4 h2 = __ldg((const float4*)(g_Z1 + (size_t)s4.z * D_EMB) + c);
    float4 h3 = __ldg((const float4*)(g_Z1 + (size_t)s4.w * D_EMB) + c);

    red_add_v4(g_S2 + (size_t)d4.x * D_EMB + c*4, make_float4(v4.x*h0.x, v4.x*h0.y, v4.x*h0.z, v4.x*h0.w));
    red_add_v4(g_S2 + (size_t)d4.y * D_EMB + c*4, make_float4(v4.y*h1.x, v4.y*h1.y, v4.y*h1.z, v4.y*h1.w));
    red_add_v4(g_S2 + (size_t)d4.z * D_EMB + c*4, make_float4(v4.z*h2.x, v4.z*h2.y, v4.z*h2.z, v4.z*h2.w));
    red_add_v4(g_S2 + (size_t)d4.w * D_EMB + c*4, make_float4(v4.w*h3.x, v4.w*h3.y, v4.w*h3.z, v4.w*h3.w));
}

// ---------------------------------------------------------------------------
// Decoder: 8 lanes per edge-group, 4 edges per thread, vector index loads.
// ---------------------------------------------------------------------------
__global__ __launch_bounds__(256) void decoder_kernel(
    const int* __restrict__ edge_index, const float* __restrict__ b2,
    float* __restrict__ out, int ne)
{
    int t = blockIdx.x * blockDim.x + threadIdx.x;
    int c = t & 7;
    int g = t >> 3;
    int base = g * 4;
    bool gvalid = (base < ne);
    int gg = gvalid ? g : (ne - 1) >> 2;     // clamp: all lanes participate in shfl
    int gb = gg * 4;

    int4 s4, d4;
    if (gb + 3 < ne) {
        s4 = __ldg((const int4*)edge_index + gg);
        d4 = __ldg((const int4*)(edge_index + ne) + gg);
    } else {
        int e1 = (gb+1 < ne) ? gb+1 : gb;
        int e2 = (gb+2 < ne) ? gb+2 : gb;
        int e3 = (gb+3 < ne) ? gb+3 : gb;
        s4 = make_int4(__ldg(edge_index+gb), __ldg(edge_index+e1),
                       __ldg(edge_index+e2), __ldg(edge_index+e3));
        d4 = make_int4(__ldg(edge_index+ne+gb), __ldg(edge_index+ne+e1),
                       __ldg(edge_index+ne+e2), __ldg(edge_index+ne+e3));
    }

    float4 bb = __ldg((const float4*)b2 + c);
    float4 a0 = __ldg((const float4*)(g_S2 + (size_t)s4.x * D_EMB) + c);
    float4 a1 = __ldg((const float4*)(g_S2 + (size_t)s4.y * D_EMB) + c);
    float4 a2 = __ldg((const float4*)(g_S2 + (size_t)s4.z * D_EMB) + c);
    float4 a3 = __ldg((const float4*)(g_S2 + (size_t)s4.w * D_EMB) + c);
    float4 b0 = __ldg((const float4*)(g_S2 + (size_t)d4.x * D_EMB) + c);
    float4 b1 = __ldg((const float4*)(g_S2 + (size_t)d4.y * D_EMB) + c);
    float4 b2v= __ldg((const float4*)(g_S2 + (size_t)d4.z * D_EMB) + c);
    float4 b3 = __ldg((const float4*)(g_S2 + (size_t)d4.w * D_EMB) + c);

    float p0 = (a0.x+bb.x)*(b0.x+bb.x) + (a0.y+bb.y)*(b0.y+bb.y)
             + (a0.z+bb.z)*(b0.z+bb.z) + (a0.w+bb.w)*(b0.w+bb.w);
    float p1 = (a1.x+bb.x)*(b1.x+bb.x) + (a1.y+bb.y)*(b1.y+bb.y)
             + (a1.z+bb.z)*(b1.z+bb.z) + (a1.w+bb.w)*(b1.w+bb.w);
    float p2 = (a2.x+bb.x)*(b2v.x+bb.x) + (a2.y+bb.y)*(b2v.y+bb.y)
             + (a2.z+bb.z)*(b2v.z+bb.z) + (a2.w+bb.w)*(b2v.w+bb.w);
    float p3 = (a3.x+bb.x)*(b3.x+bb.x) + (a3.y+bb.y)*(b3.y+bb.y)
             + (a3.z+bb.z)*(b3.z+bb.z) + (a3.w+bb.w)*(b3.w+bb.w);

    #pragma unroll
    for (int m = 1; m < 8; m <<= 1) {
        p0 += __shfl_xor_sync(0xFFFFFFFFu, p0, m);
        p1 += __shfl_xor_sync(0xFFFFFFFFu, p1, m);
        p2 += __shfl_xor_sync(0xFFFFFFFFu, p2, m);
        p3 += __shfl_xor_sync(0xFFFFFFFFu, p3, m);
    }

    if (gvalid && c == 0) {
        if (gb + 3 < ne) {
            *(float4*)(out + gb) = make_float4(p0, p1, p2, p3);
        } else {
            out[gb] = p0;
            if (gb+1 < ne) out[gb+1] = p1;
            if (gb+2 < ne) out[gb+2] = p2;
            if (gb+3 < ne) out[gb+3] = p3;
        }
    }
}

// ---------------------------------------------------------------------------
extern "C" void kernel_launch(void* const* d_in, const int* in_sizes, int n_in,
                              void* d_out, int out_size)
{
    const float* x         = (const float*)d_in[0];
    const int*   adj_src   = (const int*)  d_in[1];
    const int*   adj_dst   = (const int*)  d_in[2];
    const float* adj_val   = (const float*)d_in[3];
    const int*   edge_idx  = (const int*)  d_in[4];
    const float* W1        = (const float*)d_in[5];
    const float* b1        = (const float*)d_in[6];
    const float* W2        = (const float*)d_in[7];
    const float* b2        = (const float*)d_in[8];
    float*       out       = (float*)d_out;

    int n   = in_sizes[0] / D_IN;
    int nnz = in_sizes[3];
    int ne  = in_sizes[4] / 2;
    (void)n_in; (void)out_size;

    // GEMM1 (TF32 + cp.async, fused S1/S2 zeroing)
    cudaFuncSetAttribute(gemm1_tf32_v3,
                         cudaFuncAttributeMaxDynamicSharedMemorySize, GEMM1_SMEM);
    gemm1_tf32_v3<<<(n + 127) / 128, 256, GEMM1_SMEM>>>(x, W1, n);
    // SpMM1 (d=64): 4 edges per 16-lane group
    {
        long long groups = ((long long)nnz + 3) / 4;
        long long total  = groups * 16;
        int blocks = (int)((total + 255) / 256);
        spmm64_kernel<<<blocks, 256>>>(adj_src, adj_dst, adj_val, nnz);
    }
    // GEMM2 (fused relu + b1)
    gemm2_kernel<<<(n + 63) / 64, 256>>>(b1, W2, n);
    // SpMM2 (d=32): 4 edges per 8-lane group
    {
        long long groups = ((long long)nnz + 3) / 4;
        long long total  = groups * 8;
        int blocks = (int)((total + 255) / 256);
        spmm32_kernel<<<blocks, 256>>>(adj_src, adj_dst, adj_val, nnz);
    }
    // Decoder: 4 edges per 8-lane group
    {
        long long groups = ((long long)ne + 3) / 4;
        long long total  = groups * 8;
        int blocks = (int)((total + 255) / 256);
        decoder_kernel<<<blocks, 256>>>(edge_idx, b2, out, ne);
    }
}

// round 8
// speedup vs baseline: 1.0701x; 1.0701x over previous
#include <cuda_runtime.h>
#include <cuda_fp16.h>
#include <stdint.h>

#define D_IN   256
#define D_HID  64
#define D_EMB  32
#define MAX_NODES 100000

// Scratch (static __device__ — no allocation allowed)
__device__ __half g_Hh [MAX_NODES * D_HID];  // x @ W1            (fp16)
__device__ float  g_S1 [MAX_NODES * D_HID];  // A @ H             (fp32)
__device__ __half g_Z1h[MAX_NODES * D_EMB];  // relu(S1+b1) @ W2  (fp16)
__device__ float  g_S2 [MAX_NODES * D_EMB];  // A @ Z1            (fp32)
__device__ __half g_S2h[MAX_NODES * D_EMB];  // fp16 copy for decoder

// ---------------------------------------------------------------------------
// TF32 helpers
// ---------------------------------------------------------------------------
__device__ __forceinline__ unsigned f2tf32(float f) {
    unsigned r;
    asm("cvt.rna.tf32.f32 %0, %1;" : "=r"(r) : "f"(f));
    return r;
}
__device__ __forceinline__ unsigned bits2tf32(unsigned b) {
    unsigned r;
    asm("cvt.rna.tf32.f32 %0, %1;" : "=r"(r) : "r"(b));
    return r;
}

__device__ __forceinline__ void mma_tf32(
    float& d0, float& d1, float& d2, float& d3,
    unsigned a0, unsigned a1, unsigned a2, unsigned a3,
    unsigned b0, unsigned b1)
{
    asm volatile(
        "mma.sync.aligned.m16n8k8.row.col.f32.tf32.tf32.f32 "
        "{%0,%1,%2,%3}, {%4,%5,%6,%7}, {%8,%9}, {%0,%1,%2,%3};"
        : "+f"(d0), "+f"(d1), "+f"(d2), "+f"(d3)
        : "r"(a0), "r"(a1), "r"(a2), "r"(a3), "r"(b0), "r"(b1));
}

__device__ __forceinline__ void cp_async16(unsigned smem_addr, const void* gptr) {
    asm volatile("cp.async.cg.shared.global [%0], [%1], 16;"
                 :: "r"(smem_addr), "l"(gptr));
}

// ---------------------------------------------------------------------------
// GEMM1 (TF32 + cp.async double buffer + fused zeroing), fp16 output
//   H = x @ W1   [n,256] @ [256,64]
// ---------------------------------------------------------------------------
#define W_STRIDE 72
#define X_STRIDE 36
#define W_WORDS  (256 * W_STRIDE)
#define X_WORDS  (128 * X_STRIDE)
#define GEMM1_SMEM ((W_WORDS + 2 * X_WORDS) * 4)

__global__ __launch_bounds__(256) void gemm1_tf32_v4(
    const float* __restrict__ x, const float* __restrict__ W1, int n)
{
    extern __shared__ unsigned smem[];
    unsigned* Wsh = smem;                       // [256][72]
    float*    xsf = (float*)(smem + W_WORDS);   // [2][128][36]

    int tid  = threadIdx.x;
    int warp = tid >> 5;
    int lane = tid & 31;
    int row_base = blockIdx.x * 128;
    int wm   = warp * 16;
    int qrow = lane >> 2;
    int qcol = lane & 3;

    unsigned xs_base;
    asm("{ .reg .u64 t; cvta.to.shared.u64 t, %1; cvt.u32.u64 %0, t; }"
        : "=r"(xs_base) : "l"(xsf));

    // prefetch x chunk 0 into buffer 0
    #pragma unroll
    for (int l = 0; l < 4; l++) {
        int flat = tid + l * 256;
        int r    = flat >> 3;
        int c4   = flat & 7;
        int grow = row_base + r; if (grow >= n) grow = n - 1;
        cp_async16(xs_base + (unsigned)(r * X_STRIDE + c4 * 4) * 4,
                   x + (size_t)grow * D_IN + c4 * 4);
    }
    asm volatile("cp.async.commit_group;");

    // stage whole W1 (tf32, rna)
    #pragma unroll
    for (int l = 0; l < 16; l++) {
        int flat = tid + l * 256;
        int k  = flat >> 4;
        int cc = (flat & 15) * 4;
        float4 w = __ldg((const float4*)(W1 + (size_t)k * 64 + cc));
        Wsh[k * W_STRIDE + cc + 0] = f2tf32(w.x);
        Wsh[k * W_STRIDE + cc + 1] = f2tf32(w.y);
        Wsh[k * W_STRIDE + cc + 2] = f2tf32(w.z);
        Wsh[k * W_STRIDE + cc + 3] = f2tf32(w.w);
    }

    // fused zeroing of S1 / S2
    {
        int gtid = blockIdx.x * 256 + tid;
        int nthr = gridDim.x * 256;
        float4 z = make_float4(0.f, 0.f, 0.f, 0.f);
        for (int i = gtid; i < n * 16; i += nthr) ((float4*)g_S1)[i] = z;
        for (int i = gtid; i < n * 8;  i += nthr) ((float4*)g_S2)[i] = z;
    }

    float c[8][4];
    #pragma unroll
    for (int nt = 0; nt < 8; nt++)
        #pragma unroll
        for (int i = 0; i < 4; i++) c[nt][i] = 0.f;

    #pragma unroll
    for (int kc = 0; kc < 8; kc++) {
        if (kc + 1 < 8) {
            int buf = (kc + 1) & 1;
            #pragma unroll
            for (int l = 0; l < 4; l++) {
                int flat = tid + l * 256;
                int r    = flat >> 3;
                int c4   = flat & 7;
                int grow = row_base + r; if (grow >= n) grow = n - 1;
                cp_async16(xs_base + (unsigned)(buf * X_WORDS + r * X_STRIDE + c4 * 4) * 4,
                           x + (size_t)grow * D_IN + (kc + 1) * 32 + c4 * 4);
            }
            asm volatile("cp.async.commit_group;");
            asm volatile("cp.async.wait_group 1;");
        } else {
            asm volatile("cp.async.wait_group 0;");
        }
        __syncthreads();

        const unsigned* xb = (const unsigned*)(xsf + (kc & 1) * X_WORDS);
        #pragma unroll
        for (int k8 = 0; k8 < 4; k8++) {
            int ar = wm + qrow;
            int ac = k8 * 8 + qcol;
            unsigned a0 = bits2tf32(xb[(ar    ) * X_STRIDE + ac    ]);
            unsigned a1 = bits2tf32(xb[(ar + 8) * X_STRIDE + ac    ]);
            unsigned a2 = bits2tf32(xb[(ar    ) * X_STRIDE + ac + 4]);
            unsigned a3 = bits2tf32(xb[(ar + 8) * X_STRIDE + ac + 4]);
            int kg = kc * 32 + k8 * 8 + qcol;
            #pragma unroll
            for (int nt = 0; nt < 8; nt++) {
                unsigned b0 = Wsh[(kg    ) * W_STRIDE + nt * 8 + qrow];
                unsigned b1 = Wsh[(kg + 4) * W_STRIDE + nt * 8 + qrow];
                mma_tf32(c[nt][0], c[nt][1], c[nt][2], c[nt][3],
                         a0, a1, a2, a3, b0, b1);
            }
        }
        __syncthreads();
    }

    int r0 = row_base + wm + qrow;
    int cb = qcol * 2;
    #pragma unroll
    for (int nt = 0; nt < 8; nt++) {
        if (r0 < n)
            *(__half2*)(g_Hh + (size_t)r0 * D_HID + nt*8 + cb) =
                __floats2half2_rn(c[nt][0], c[nt][1]);
        if (r0 + 8 < n)
            *(__half2*)(g_Hh + (size_t)(r0 + 8) * D_HID + nt*8 + cb) =
                __floats2half2_rn(c[nt][2], c[nt][3]);
    }
}

// ---------------------------------------------------------------------------
// red.v4 helper
// ---------------------------------------------------------------------------
__device__ __forceinline__ void red_add_v4(float* p, float4 v) {
    asm volatile("red.global.add.v4.f32 [%0], {%1,%2,%3,%4};"
                 :: "l"(p), "f"(v.x), "f"(v.y), "f"(v.z), "f"(v.w)
                 : "memory");
}

// ---------------------------------------------------------------------------
// SpMM d=64 (fp16 gather): 16 lanes per edge, 4 edges per thread.
// Lane c reads 4 halves (8B) = channels c*4..c*4+3.
// ---------------------------------------------------------------------------
__global__ __launch_bounds__(256) void spmm64_kernel(
    const int* __restrict__ src, const int* __restrict__ dst,
    const float* __restrict__ val, int nnz)
{
    int t = blockIdx.x * blockDim.x + threadIdx.x;
    int c = t & 15;
    int base = (t >> 4) * 4;
    if (base >= nnz) return;

    int   s[4], d[4];
    float v[4];
    #pragma unroll
    for (int j = 0; j < 4; j++) {
        int e = base + j;
        bool ok = (e < nnz);
        int ec = ok ? e : base;
        s[j] = __ldg(src + ec);
        d[j] = __ldg(dst + ec);
        v[j] = ok ? __ldg(val + ec) : 0.f;
    }
    uint2 raw[4];
    #pragma unroll
    for (int j = 0; j < 4; j++)
        raw[j] = __ldg((const uint2*)(g_Hh + (size_t)s[j] * D_HID) + c);
    #pragma unroll
    for (int j = 0; j < 4; j++) {
        __half2 h0 = *(__half2*)&raw[j].x;
        __half2 h1 = *(__half2*)&raw[j].y;
        float2 f0 = __half22float2(h0);
        float2 f1 = __half22float2(h1);
        red_add_v4(g_S1 + (size_t)d[j] * D_HID + c * 4,
                   make_float4(v[j]*f0.x, v[j]*f0.y, v[j]*f1.x, v[j]*f1.y));
    }
}

// ---------------------------------------------------------------------------
// GEMM2: Z1 = relu(S1 + b1) @ W2   [n,64] @ [64,32], fp16 output
// ---------------------------------------------------------------------------
__global__ __launch_bounds__(256) void gemm2_kernel(
    const float* __restrict__ b1, const float* __restrict__ W2, int n)
{
    __shared__ float zs[64][65];
    __shared__ float ws[64][32];

    int tid = threadIdx.x;
    int row_base = blockIdx.x * 64;

    #pragma unroll
    for (int l = 0; l < 4; l++) {
        int flat = tid + l * 256;
        int r  = flat >> 4;
        int c4 = flat & 15;
        float4 v = make_float4(0.f,0.f,0.f,0.f);
        if (row_base + r < n)
            v = *(const float4*)(g_S1 + (size_t)row_base * D_HID + (size_t)flat * 4);
        float4 bb = __ldg((const float4*)b1 + c4);
        v.x = fmaxf(v.x + bb.x, 0.f);
        v.y = fmaxf(v.y + bb.y, 0.f);
        v.z = fmaxf(v.z + bb.z, 0.f);
        v.w = fmaxf(v.w + bb.w, 0.f);
        zs[r][c4*4+0] = v.x; zs[r][c4*4+1] = v.y;
        zs[r][c4*4+2] = v.z; zs[r][c4*4+3] = v.w;
    }
    #pragma unroll
    for (int l = 0; l < 2; l++) {
        int flat = tid + l * 256;
        ((float4*)&ws[0][0])[flat] = __ldg((const float4*)W2 + flat);
    }
    __syncthreads();

    int ty = tid >> 3;
    int tx = tid & 7;
    int col = tx * 4;

    float a00=0,a01=0,a02=0,a03=0;
    float a10=0,a11=0,a12=0,a13=0;

    #pragma unroll 16
    for (int kk = 0; kk < 64; kk++) {
        float z0 = zs[ty*2+0][kk];
        float z1 = zs[ty*2+1][kk];
        float4 b = *(float4*)&ws[kk][col];
        a00 += z0*b.x; a01 += z0*b.y; a02 += z0*b.z; a03 += z0*b.w;
        a10 += z1*b.x; a11 += z1*b.y; a12 += z1*b.z; a13 += z1*b.w;
    }

    int r0 = row_base + ty*2;
    if (r0 + 0 < n) {
        *(__half2*)(g_Z1h + (size_t)(r0+0)*D_EMB + col)     = __floats2half2_rn(a00, a01);
        *(__half2*)(g_Z1h + (size_t)(r0+0)*D_EMB + col + 2) = __floats2half2_rn(a02, a03);
    }
    if (r0 + 1 < n) {
        *(__half2*)(g_Z1h + (size_t)(r0+1)*D_EMB + col)     = __floats2half2_rn(a10, a11);
        *(__half2*)(g_Z1h + (size_t)(r0+1)*D_EMB + col + 2) = __floats2half2_rn(a12, a13);
    }
}

// ---------------------------------------------------------------------------
// SpMM d=32 (fp16 gather): 8 lanes per edge, 4 edges per thread.
// ---------------------------------------------------------------------------
__global__ __launch_bounds__(256) void spmm32_kernel(
    const int* __restrict__ src, const int* __restrict__ dst,
    const float* __restrict__ val, int nnz)
{
    int t = blockIdx.x * blockDim.x + threadIdx.x;
    int c = t & 7;
    int base = (t >> 3) * 4;
    if (base >= nnz) return;

    int   s[4], d[4];
    float v[4];
    #pragma unroll
    for (int j = 0; j < 4; j++) {
        int e = base + j;
        bool ok = (e < nnz);
        int ec = ok ? e : base;
        s[j] = __ldg(src + ec);
        d[j] = __ldg(dst + ec);
        v[j] = ok ? __ldg(val + ec) : 0.f;
    }
    uint2 raw[4];
    #pragma unroll
    for (int j = 0; j < 4; j++)
        raw[j] = __ldg((const uint2*)(g_Z1h + (size_t)s[j] * D_EMB) + c);
    #pragma unroll
    for (int j = 0; j < 4; j++) {
        __half2 h0 = *(__half2*)&raw[j].x;
        __half2 h1 = *(__half2*)&raw[j].y;
        float2 f0 = __half22float2(h0);
        float2 f1 = __half22float2(h1);
        red_add_v4(g_S2 + (size_t)d[j] * D_EMB + c * 4,
                   make_float4(v[j]*f0.x, v[j]*f0.y, v[j]*f1.x, v[j]*f1.y));
    }
}

// ---------------------------------------------------------------------------
// S2 fp32 -> fp16 conversion for the decoder gathers.
// ---------------------------------------------------------------------------
__global__ __launch_bounds__(256) void s2half_kernel(int n4) {
    int i = blockIdx.x * blockDim.x + threadIdx.x;  // over n*8 float4 groups
    if (i >= n4) return;
    float4 v = ((const float4*)g_S2)[i];
    ((__half2*)g_S2h)[i*2    ] = __floats2half2_rn(v.x, v.y);
    ((__half2*)g_S2h)[i*2 + 1] = __floats2half2_rn(v.z, v.w);
}

// ---------------------------------------------------------------------------
// Decoder (fp16 gathers): 8 lanes per edge, 2 edges per thread.
// ---------------------------------------------------------------------------
__global__ __launch_bounds__(256) void decoder_kernel(
    const int* __restrict__ edge_index, const float* __restrict__ b2,
    float* __restrict__ out, int ne)
{
    int t = blockIdx.x * blockDim.x + threadIdx.x;
    int c = t & 7;
    int base = (t >> 3) * 2;
    if (base >= ne) return;

    int e0 = base;
    int e1 = (base + 1 < ne) ? base + 1 : base;

    int s0 = __ldg(edge_index + e0);
    int d0 = __ldg(edge_index + ne + e0);
    int s1 = __ldg(edge_index + e1);
    int d1 = __ldg(edge_index + ne + e1);

    uint2 ra0 = __ldg((const uint2*)(g_S2h + (size_t)s0 * D_EMB) + c);
    uint2 rb0 = __ldg((const uint2*)(g_S2h + (size_t)d0 * D_EMB) + c);
    uint2 ra1 = __ldg((const uint2*)(g_S2h + (size_t)s1 * D_EMB) + c);
    uint2 rb1 = __ldg((const uint2*)(g_S2h + (size_t)d1 * D_EMB) + c);

    float4 bb = __ldg((const float4*)b2 + c);

    float2 a0l = __half22float2(*(__half2*)&ra0.x);
    float2 a0h = __half22float2(*(__half2*)&ra0.y);
    float2 b0l = __half22float2(*(__half2*)&rb0.x);
    float2 b0h = __half22float2(*(__half2*)&rb0.y);
    float2 a1l = __half22float2(*(__half2*)&ra1.x);
    float2 a1h = __half22float2(*(__half2*)&ra1.y);
    float2 b1l = __half22float2(*(__half2*)&rb1.x);
    float2 b1h = __half22float2(*(__half2*)&rb1.y);

    float p0 = (a0l.x + bb.x) * (b0l.x + bb.x)
             + (a0l.y + bb.y) * (b0l.y + bb.y)
             + (a0h.x + bb.z) * (b0h.x + bb.z)
             + (a0h.y + bb.w) * (b0h.y + bb.w);
    float p1 = (a1l.x + bb.x) * (b1l.x + bb.x)
             + (a1l.y + bb.y) * (b1l.y + bb.y)
             + (a1h.x + bb.z) * (b1h.x + bb.z)
             + (a1h.y + bb.w) * (b1h.y + bb.w);

    #pragma unroll
    for (int m = 1; m < 8; m <<= 1) {
        p0 += __shfl_xor_sync(0xFFFFFFFFu, p0, m);
        p1 += __shfl_xor_sync(0xFFFFFFFFu, p1, m);
    }

    if (c == 0) {
        out[e0] = p0;
        if (base + 1 < ne) out[base + 1] = p1;
    }
}

// ---------------------------------------------------------------------------
extern "C" void kernel_launch(void* const* d_in, const int* in_sizes, int n_in,
                              void* d_out, int out_size)
{
    const float* x         = (const float*)d_in[0];
    const int*   adj_src   = (const int*)  d_in[1];
    const int*   adj_dst   = (const int*)  d_in[2];
    const float* adj_val   = (const float*)d_in[3];
    const int*   edge_idx  = (const int*)  d_in[4];
    const float* W1        = (const float*)d_in[5];
    const float* b1        = (const float*)d_in[6];
    const float* W2        = (const float*)d_in[7];
    const float* b2        = (const float*)d_in[8];
    float*       out       = (float*)d_out;

    int n   = in_sizes[0] / D_IN;
    int nnz = in_sizes[3];
    int ne  = in_sizes[4] / 2;
    (void)n_in; (void)out_size;

    // GEMM1 (TF32 + cp.async, fused S1/S2 zeroing, fp16 H)
    cudaFuncSetAttribute(gemm1_tf32_v4,
                         cudaFuncAttributeMaxDynamicSharedMemorySize, GEMM1_SMEM);
    gemm1_tf32_v4<<<(n + 127) / 128, 256, GEMM1_SMEM>>>(x, W1, n);
    // SpMM1 (d=64): 4 edges per 16-lane group
    {
        long long groups = ((long long)nnz + 3) / 4;
        long long total  = groups * 16;
        int blocks = (int)((total + 255) / 256);
        spmm64_kernel<<<blocks, 256>>>(adj_src, adj_dst, adj_val, nnz);
    }
    // GEMM2 (fused relu + b1, fp16 Z1)
    gemm2_kernel<<<(n + 63) / 64, 256>>>(b1, W2, n);
    // SpMM2 (d=32): 4 edges per 8-lane group
    {
        long long groups = ((long long)nnz + 3) / 4;
        long long total  = groups * 8;
        int blocks = (int)((total + 255) / 256);
        spmm32_kernel<<<blocks, 256>>>(adj_src, adj_dst, adj_val, nnz);
    }
    // S2 -> fp16
    {
        int n4 = n * 8;
        s2half_kernel<<<(n4 + 255) / 256, 256>>>(n4);
    }
    // Decoder: 2 edges per 8-lane group
    {
        long long groups = ((long long)ne + 1) / 2;
        long long total  = groups * 8;
        int blocks = (int)((total + 255) / 256);
        decoder_kernel<<<blocks, 256>>>(edge_idx, b2, out, ne);
    }
}